// round 1
// baseline (speedup 1.0000x reference)
#include <cuda_runtime.h>

// ---------------- problem constants ----------------
#define BATCH 4
#define NQ    4096
#define NK    1024
#define NH    16
#define HD    64
#define QD    1024   // QUERY_DIM
#define KD    768    // KEY_DIM
#define ATT_SCALE 0.125f  // 64^-0.5

// ---------------- scratch (device globals, no allocation) ----------------
__device__ float g_Qp[(size_t)BATCH * NQ * QD];  // projected Q  [B*Nq, 1024]
__device__ float g_Kp[(size_t)BATCH * NK * QD];  // projected K  [B*Nk, 1024]
__device__ float g_Vp[(size_t)BATCH * NK * QD];  // projected V  [B*Nk, 1024]
__device__ float g_AO[(size_t)BATCH * NQ * QD];  // attention out [B*Nq, 1024]

// ============================================================
// Tiled SGEMM with fused bias: C[M,N] = A[M,K] @ B[K,N] + bias
// BM=128, BN=128, BK=16, 256 threads, 8x8 per thread.
// Requires M%128==0, N%128==0, K%16==0 (true for all our shapes).
// ============================================================
#define GBM 128
#define GBN 128
#define GBK 16

__global__ __launch_bounds__(256) void sgemm_bias(
    const float* __restrict__ A, const float* __restrict__ B,
    const float* __restrict__ bias, float* __restrict__ C,
    int M, int N, int K)
{
    __shared__ float As[GBK][GBM];   // transposed A tile
    __shared__ float Bs[GBK][GBN];

    const int t   = threadIdx.x;
    const int tx  = t & 15;          // 0..15
    const int ty  = t >> 4;          // 0..15
    const int row0 = blockIdx.y * GBM;
    const int col0 = blockIdx.x * GBN;

    // A-load mapping: thread handles rows (t>>2) and (t>>2)+64, k-quad (t&3)*4
    const int arow = t >> 2;
    const int ak4  = (t & 3) * 4;
    // B-load mapping: row t>>5 (and +8), col quad (t&31)*4
    const int brow = t >> 5;
    const int bc4  = (t & 31) * 4;

    const float* Aptr = A + (size_t)row0 * K;
    const float* Bptr = B + col0;

    float acc[8][8];
#pragma unroll
    for (int i = 0; i < 8; i++)
#pragma unroll
        for (int j = 0; j < 8; j++) acc[i][j] = 0.f;

    for (int kt = 0; kt < K; kt += GBK) {
#pragma unroll
        for (int rr = 0; rr < 2; rr++) {
            int r = arow + rr * 64;
            float4 av = *(const float4*)(Aptr + (size_t)r * K + kt + ak4);
            As[ak4 + 0][r] = av.x;
            As[ak4 + 1][r] = av.y;
            As[ak4 + 2][r] = av.z;
            As[ak4 + 3][r] = av.w;
        }
#pragma unroll
        for (int rr = 0; rr < 2; rr++) {
            int r = brow + rr * 8;
            float4 bv = *(const float4*)(Bptr + (size_t)(kt + r) * N + bc4);
            *(float4*)&Bs[r][bc4] = bv;
        }
        __syncthreads();

#pragma unroll
        for (int kk = 0; kk < GBK; kk++) {
            float ar[8], br[8];
            *(float4*)&ar[0] = *(const float4*)&As[kk][ty * 8];
            *(float4*)&ar[4] = *(const float4*)&As[kk][ty * 8 + 4];
            *(float4*)&br[0] = *(const float4*)&Bs[kk][tx * 8];
            *(float4*)&br[4] = *(const float4*)&Bs[kk][tx * 8 + 4];
#pragma unroll
            for (int i = 0; i < 8; i++)
#pragma unroll
                for (int j = 0; j < 8; j++)
                    acc[i][j] += ar[i] * br[j];
        }
        __syncthreads();
    }

#pragma unroll
    for (int i = 0; i < 8; i++) {
        int r = row0 + ty * 8 + i;
#pragma unroll
        for (int j = 0; j < 8; j += 4) {
            int c = col0 + tx * 8 + j;
            float4 o;
            o.x = acc[i][j + 0] + bias[c + 0];
            o.y = acc[i][j + 1] + bias[c + 1];
            o.z = acc[i][j + 2] + bias[c + 2];
            o.w = acc[i][j + 3] + bias[c + 3];
            *(float4*)&C[(size_t)r * N + c] = o;
        }
    }
}

// ============================================================
// Flash attention, fp32. One block = 64 q rows of one (b,h).
// 256 threads: thread t -> row r=t>>2, col-group cg=t&3 (16 cols).
// smem (dynamic): Qs[64][65], KP[64][68] (K^T, reused as P), Vs[64][64]
// ============================================================
#define QS_STRIDE 65
#define KP_STRIDE 68
#define VS_STRIDE 64
#define ATTN_SMEM_FLOATS (64 * QS_STRIDE + 64 * KP_STRIDE + 64 * VS_STRIDE)
#define ATTN_SMEM_BYTES  (ATTN_SMEM_FLOATS * 4)

__global__ __launch_bounds__(256) void attn_kernel(
    const float* __restrict__ Qp, const float* __restrict__ Kp,
    const float* __restrict__ Vp, float* __restrict__ AO)
{
    extern __shared__ float sm[];
    float* Qs = sm;                        // 64 x 65
    float* KP = sm + 64 * QS_STRIDE;       // 64 x 68  (K transposed, then P)
    float* Vs = KP + 64 * KP_STRIDE;       // 64 x 64

    const int t  = threadIdx.x;
    const int r  = t >> 2;                 // 0..63  (q row within tile)
    const int cg = t & 3;                  // col group: 16 cols each
    const int q0 = blockIdx.x * 64;
    const int h  = blockIdx.y;
    const int b  = blockIdx.z;

    const float* Qg = Qp + ((size_t)(b * NQ + q0)) * QD + h * HD;
    const float* Kg = Kp + ((size_t)(b * NK)) * QD + h * HD;
    const float* Vg = Vp + ((size_t)(b * NK)) * QD + h * HD;

    // ---- load Q tile (pre-scaled) ----
    {
        const int rr = t >> 2, dg = t & 3;
#pragma unroll
        for (int w = 0; w < 4; w++) {
            float4 qv = *(const float4*)(Qg + (size_t)rr * QD + dg * 16 + w * 4);
            float* q = &Qs[rr * QS_STRIDE + dg * 16 + w * 4];
            q[0] = qv.x * ATT_SCALE;
            q[1] = qv.y * ATT_SCALE;
            q[2] = qv.z * ATT_SCALE;
            q[3] = qv.w * ATT_SCALE;
        }
    }

    float m = -1e30f, l = 0.f;
    float acc[16];
#pragma unroll
    for (int j = 0; j < 16; j++) acc[j] = 0.f;

    for (int n0 = 0; n0 < NK; n0 += 64) {
        __syncthreads();   // previous iteration finished reading KP/Vs

        // ---- load K chunk (transposed) and V chunk ----
        {
            const int i = t >> 2, dg = t & 3;
#pragma unroll
            for (int w = 0; w < 4; w++) {
                int d = dg * 16 + w * 4;
                float4 kv = *(const float4*)(Kg + (size_t)(n0 + i) * QD + d);
                KP[(d + 0) * KP_STRIDE + i] = kv.x;
                KP[(d + 1) * KP_STRIDE + i] = kv.y;
                KP[(d + 2) * KP_STRIDE + i] = kv.z;
                KP[(d + 3) * KP_STRIDE + i] = kv.w;
                float4 vv = *(const float4*)(Vg + (size_t)(n0 + i) * QD + d);
                *(float4*)&Vs[i * VS_STRIDE + d] = vv;
            }
        }
        __syncthreads();

        // ---- S = Q K^T : 16 columns per thread ----
        float s[16];
#pragma unroll
        for (int j = 0; j < 16; j++) s[j] = 0.f;
#pragma unroll 8
        for (int d = 0; d < 64; d++) {
            float q = Qs[r * QS_STRIDE + d];
            float kv[16];
            *(float4*)&kv[0]  = *(const float4*)&KP[d * KP_STRIDE + cg * 16 + 0];
            *(float4*)&kv[4]  = *(const float4*)&KP[d * KP_STRIDE + cg * 16 + 4];
            *(float4*)&kv[8]  = *(const float4*)&KP[d * KP_STRIDE + cg * 16 + 8];
            *(float4*)&kv[12] = *(const float4*)&KP[d * KP_STRIDE + cg * 16 + 12];
#pragma unroll
            for (int j = 0; j < 16; j++) s[j] += q * kv[j];
        }

        // ---- online softmax update (4 threads per row, same warp quad) ----
        float cmax = s[0];
#pragma unroll
        for (int j = 1; j < 16; j++) cmax = fmaxf(cmax, s[j]);
        cmax = fmaxf(cmax, __shfl_xor_sync(0xffffffffu, cmax, 1));
        cmax = fmaxf(cmax, __shfl_xor_sync(0xffffffffu, cmax, 2));
        float mnew = fmaxf(m, cmax);
        float psum = 0.f;
#pragma unroll
        for (int j = 0; j < 16; j++) {
            s[j] = __expf(s[j] - mnew);
            psum += s[j];
        }
        psum += __shfl_xor_sync(0xffffffffu, psum, 1);
        psum += __shfl_xor_sync(0xffffffffu, psum, 2);
        float alpha = __expf(m - mnew);
        l = l * alpha + psum;
#pragma unroll
        for (int j = 0; j < 16; j++) acc[j] *= alpha;
        m = mnew;

        __syncthreads();   // everyone done reading KP as K^T

        // ---- stage P into KP ----
        *(float4*)&KP[r * KP_STRIDE + cg * 16 + 0]  = make_float4(s[0],  s[1],  s[2],  s[3]);
        *(float4*)&KP[r * KP_STRIDE + cg * 16 + 4]  = make_float4(s[4],  s[5],  s[6],  s[7]);
        *(float4*)&KP[r * KP_STRIDE + cg * 16 + 8]  = make_float4(s[8],  s[9],  s[10], s[11]);
        *(float4*)&KP[r * KP_STRIDE + cg * 16 + 12] = make_float4(s[12], s[13], s[14], s[15]);
        __syncthreads();

        // ---- O += P @ V : 16 output dims per thread ----
#pragma unroll 8
        for (int kk = 0; kk < 64; kk++) {
            float p = KP[r * KP_STRIDE + kk];
            float vv[16];
            *(float4*)&vv[0]  = *(const float4*)&Vs[kk * VS_STRIDE + cg * 16 + 0];
            *(float4*)&vv[4]  = *(const float4*)&Vs[kk * VS_STRIDE + cg * 16 + 4];
            *(float4*)&vv[8]  = *(const float4*)&Vs[kk * VS_STRIDE + cg * 16 + 8];
            *(float4*)&vv[12] = *(const float4*)&Vs[kk * VS_STRIDE + cg * 16 + 12];
#pragma unroll
            for (int j = 0; j < 16; j++) acc[j] += p * vv[j];
        }
    }

    const float inv = 1.0f / l;
    float* Og = AO + ((size_t)(b * NQ + q0 + r)) * QD + h * HD + cg * 16;
    *(float4*)&Og[0]  = make_float4(acc[0]*inv,  acc[1]*inv,  acc[2]*inv,  acc[3]*inv);
    *(float4*)&Og[4]  = make_float4(acc[4]*inv,  acc[5]*inv,  acc[6]*inv,  acc[7]*inv);
    *(float4*)&Og[8]  = make_float4(acc[8]*inv,  acc[9]*inv,  acc[10]*inv, acc[11]*inv);
    *(float4*)&Og[12] = make_float4(acc[12]*inv, acc[13]*inv, acc[14]*inv, acc[15]*inv);
}

// ============================================================
// kernel_launch: 5 kernels on the default stream.
// ============================================================
extern "C" void kernel_launch(void* const* d_in, const int* in_sizes, int n_in,
                              void* d_out, int out_size)
{
    const float* query = (const float*)d_in[0];
    const float* key   = (const float*)d_in[1];
    const float* value = (const float*)d_in[2];
    const float* Wq    = (const float*)d_in[3];
    const float* bq    = (const float*)d_in[4];
    const float* Wk    = (const float*)d_in[5];
    const float* bk    = (const float*)d_in[6];
    const float* Wv    = (const float*)d_in[7];
    const float* bv    = (const float*)d_in[8];
    const float* Wo    = (const float*)d_in[9];
    const float* bo    = (const float*)d_in[10];
    float* out = (float*)d_out;

    float *Qp, *Kp, *Vp, *AO;
    cudaGetSymbolAddress((void**)&Qp, g_Qp);
    cudaGetSymbolAddress((void**)&Kp, g_Kp);
    cudaGetSymbolAddress((void**)&Vp, g_Vp);
    cudaGetSymbolAddress((void**)&AO, g_AO);

    cudaFuncSetAttribute(attn_kernel,
                         cudaFuncAttributeMaxDynamicSharedMemorySize,
                         ATTN_SMEM_BYTES);

    dim3 blk(256);

    // Q projection: [16384,1024] x [1024,1024]
    sgemm_bias<<<dim3(QD / GBN, (BATCH * NQ) / GBM), blk>>>(
        query, Wq, bq, Qp, BATCH * NQ, QD, QD);
    // K projection: [4096,768] x [768,1024]
    sgemm_bias<<<dim3(QD / GBN, (BATCH * NK) / GBM), blk>>>(
        key, Wk, bk, Kp, BATCH * NK, QD, KD);
    // V projection
    sgemm_bias<<<dim3(QD / GBN, (BATCH * NK) / GBM), blk>>>(
        value, Wv, bv, Vp, BATCH * NK, QD, KD);

    // attention: grid (Nq/64, heads, batch)
    attn_kernel<<<dim3(NQ / 64, NH, BATCH), blk, ATTN_SMEM_BYTES>>>(Qp, Kp, Vp, AO);

    // output projection: [16384,1024] x [1024,1024] -> d_out
    sgemm_bias<<<dim3(QD / GBN, (BATCH * NQ) / GBM), blk>>>(
        AO, Wo, bo, out, BATCH * NQ, QD, QD);
}